// round 10
// baseline (speedup 1.0000x reference)
#include <cuda_runtime.h>
#include <cuda_fp16.h>
#include <math.h>

#define NN 100000
#define DD 128
#define AA 4096
#define SS 512
// exp(sim/TEMP) = exp2(sim * 10 * log2(e)) = exp2(sim * 14.4269504089f)

// Scratch (no device mallocs allowed)
__device__ __half g_xh[(size_t)NN * DD];   // normalized fp16 features, 25.6 MB
__device__ float  g_aloss[AA];
__device__ int    g_done = 0;              // ticket counter for last-block reduce

__device__ __forceinline__ float ex2_approx(float v) {
    float r;
    asm("ex2.approx.ftz.f32 %0, %1;" : "=f"(r) : "f"(v));
    return r;
}

// ---------------------------------------------------------------------------
// Kernel 1: fused normalize + fp16 convert. FOUR rows per warp (MLP=4).
// __ldcs: x read exactly once -> evict-first, keep L2 warm for g_xh.
// ---------------------------------------------------------------------------
__global__ void norm_convert_kernel(const float* __restrict__ x) {
    int warp = (blockIdx.x * blockDim.x + threadIdx.x) >> 5;
    int lane = threadIdx.x & 31;
    int r0 = warp * 4;
    if (r0 >= NN) return;

    float4 v[4];
    bool has[4];
#pragma unroll
    for (int k = 0; k < 4; k++) {
        int r = r0 + k;
        has[k] = (r < NN);
        v[k] = has[k]
            ? __ldcs(reinterpret_cast<const float4*>(x + (size_t)r * DD) + lane)
            : make_float4(0.f, 0.f, 0.f, 0.f);
    }

    float s[4];
#pragma unroll
    for (int k = 0; k < 4; k++)
        s[k] = v[k].x * v[k].x + v[k].y * v[k].y + v[k].z * v[k].z + v[k].w * v[k].w;

#pragma unroll
    for (int o = 16; o; o >>= 1) {
#pragma unroll
        for (int k = 0; k < 4; k++)
            s[k] += __shfl_xor_sync(0xFFFFFFFFu, s[k], o);
    }

#pragma unroll
    for (int k = 0; k < 4; k++) {
        if (!has[k]) continue;
        float inv = rsqrtf(s[k]);
        __half2 h[2];
        h[0] = __floats2half2_rn(v[k].x * inv, v[k].y * inv);
        h[1] = __floats2half2_rn(v[k].z * inv, v[k].w * inv);
        reinterpret_cast<uint2*>(g_xh + (size_t)(r0 + k) * DD)[lane] =
            *reinterpret_cast<uint2*>(h);
    }
}

// ---------------------------------------------------------------------------
// Kernel 2: one block (8 warps) per anchor. FOUR lanes per sample:
// each lane owns 64 B (4 x float4) of the 256 B row -> 8 independent samples
// per warp (8 interleaved dependency chains), and the cross-lane reduce is
// only 2 SHFLs. Coalescing: each LDG.128 reads 8 x 64 B contiguous segments.
// Double-buffered prefetch keeps next iteration's 4 LDGs in flight.
// ---------------------------------------------------------------------------
__global__ __launch_bounds__(256) void loss_kernel(
    const int* __restrict__ y,
    const int* __restrict__ anchors,
    const int* __restrict__ sampled,
    float* __restrict__ out)
{
    __shared__ int2  s_iy[SS];               // (sample index, sample label)
    __shared__ float s_num[64], s_den[64], s_cnt[64];
    __shared__ int   s_last;
    __shared__ float s_red[256];

    int a    = blockIdx.x;
    int tid  = threadIdx.x;
    int lane = tid & 31;
    int warp = tid >> 5;     // 0..7
    int grp  = lane >> 2;    // sample group within warp (0..7)
    int gl   = lane & 3;     // lane within group

    // Stage sample indices + labels packed as int2 (random 4B gathers batched
    // here with 256 threads of MLP, out of the hot loop).
    for (int i = tid; i < SS; i += 256) {
        int si = sampled[(size_t)a * SS + i];
        s_iy[i] = make_int2(si, y[si]);
    }

    int ai = anchors[a];
    int ay = y[ai];

    // Anchor fragment: lane gl owns bytes [j*64 + gl*16) j=0..3  (4 float4)
    float4 af[4];
    {
        const float4* row4 = reinterpret_cast<const float4*>(g_xh + (size_t)ai * DD);
#pragma unroll
        for (int j = 0; j < 4; j++) af[j] = row4[j * 4 + gl];
    }
    __syncthreads();

    // This group's sample slot: sample id = it*64 + warp*8 + grp
    const int off = warp * 8 + grp;
    float num = 0.0f, den = 0.0f, cnt = 0.0f;

    // Double buffer: current + next sample fragment (4 float4) + label
    float4 cur[4], nxt[4];
    int ycur, ynxt;
    {
        int2 iy = s_iy[off];
        const float4* r4 = reinterpret_cast<const float4*>(g_xh + (size_t)iy.x * DD);
#pragma unroll
        for (int j = 0; j < 4; j++) cur[j] = r4[j * 4 + gl];
        ycur = iy.y;
    }

#pragma unroll
    for (int it = 0; it < 8; it++) {         // 8 iterations x 64 samples
        if (it + 1 < 8) {
            int2 iy = s_iy[(it + 1) * 64 + off];
            const float4* r4 = reinterpret_cast<const float4*>(g_xh + (size_t)iy.x * DD);
#pragma unroll
            for (int j = 0; j < 4; j++) nxt[j] = r4[j * 4 + gl];
            ynxt = iy.y;
        }

        // fp16x2 dot: 4 parallel accumulators, each chain depth 4
        const __half2* a0 = reinterpret_cast<const __half2*>(&af[0]);
        const __half2* s0 = reinterpret_cast<const __half2*>(&cur[0]);
        __half2 acc0 = __hmul2(a0[0], s0[0]);
        __half2 acc1 = __hmul2(a0[1], s0[1]);
        __half2 acc2 = __hmul2(a0[2], s0[2]);
        __half2 acc3 = __hmul2(a0[3], s0[3]);
#pragma unroll
        for (int j = 1; j < 4; j++) {
            const __half2* aj = reinterpret_cast<const __half2*>(&af[j]);
            const __half2* sj = reinterpret_cast<const __half2*>(&cur[j]);
            acc0 = __hfma2(aj[0], sj[0], acc0);
            acc1 = __hfma2(aj[1], sj[1], acc1);
            acc2 = __hfma2(aj[2], sj[2], acc2);
            acc3 = __hfma2(aj[3], sj[3], acc3);
        }
        __half2 h = __hadd2(__hadd2(acc0, acc1), __hadd2(acc2, acc3));
        float2 hf = __half22float2(h);
        float d = hf.x + hf.y;
        // 4-lane reduce (xor 2, 1 stay within the group)
        d += __shfl_xor_sync(0xFFFFFFFFu, d, 2);
        d += __shfl_xor_sync(0xFFFFFFFFu, d, 1);
        float e = ex2_approx(d * 14.4269504089f);   // exp(d * 10)
        den += e;
        if (ycur == ay) { num += e; cnt += 1.0f; }

        if (it + 1 < 8) {
#pragma unroll
            for (int j = 0; j < 4; j++) cur[j] = nxt[j];
            ycur = ynxt;
        }
    }

    // Per-group sums are uniform within the 4-lane group
    if (gl == 0) { s_num[off] = num; s_den[off] = den; s_cnt[off] = cnt; }
    __syncthreads();

    if (tid == 0) {
        float nm = 0.0f, dn = 0.0f, c = 0.0f;
#pragma unroll
        for (int k = 0; k < 64; k++) { nm += s_num[k]; dn += s_den[k]; c += s_cnt[k]; }
        float loss = 0.0f;
        if (c > 0.0f) loss = (logf(dn) - logf(nm)) / c;  // -log(num/den)/cnt
        g_aloss[a] = loss;
        __threadfence();
        int t = atomicAdd(&g_done, 1);
        s_last = (t == AA - 1) ? 1 : 0;
    }
    __syncthreads();

    // Last block to finish: deterministic fixed-order reduction of g_aloss.
    if (s_last) {
        float s = 0.0f;
        for (int i = tid; i < AA; i += 256) s += g_aloss[i];
        s_red[tid] = s;
        __syncthreads();
        for (int o = 128; o; o >>= 1) {
            if (tid < o) s_red[tid] += s_red[tid + o];
            __syncthreads();
        }
        if (tid == 0) {
            out[0] = s_red[0];
            g_done = 0;                      // reset for next graph replay
        }
    }
}

extern "C" void kernel_launch(void* const* d_in, const int* in_sizes, int n_in,
                              void* d_out, int out_size) {
    const float* x       = (const float*)d_in[0];
    const int*   y       = (const int*)  d_in[1];
    const int*   anchors = (const int*)  d_in[2];
    const int*   sampled = (const int*)  d_in[3];
    float*       out     = (float*)d_out;

    (void)in_sizes; (void)n_in; (void)out_size;

    // 4 rows per warp -> 32 rows per 256-thread block
    norm_convert_kernel<<<(NN + 31) / 32, 256>>>(x);
    loss_kernel<<<AA, 256>>>(y, anchors, sampled, out);
}

// round 14
// speedup vs baseline: 1.0656x; 1.0656x over previous
#include <cuda_runtime.h>
#include <cuda_fp16.h>
#include <math.h>

#define NN 100000
#define DD 128
#define AA 4096
#define SS 512
// exp(sim/TEMP) = exp2(sim * 10 * log2(e)) = exp2(sim * 14.4269504089f)

// Scratch (no device mallocs allowed)
__device__ __half g_xh[(size_t)NN * DD];   // normalized fp16 features, 25.6 MB
__device__ float  g_aloss[AA];
__device__ int    g_done = 0;              // ticket counter for last-block reduce

__device__ __forceinline__ float ex2_approx(float v) {
    float r;
    asm("ex2.approx.ftz.f32 %0, %1;" : "=f"(r) : "f"(v));
    return r;
}

// ---------------------------------------------------------------------------
// Kernel 1: fused normalize + fp16 convert. FOUR rows per warp (MLP=4).
// __ldcs: x read exactly once -> evict-first, keep L2 warm for g_xh.
// ---------------------------------------------------------------------------
__global__ void norm_convert_kernel(const float* __restrict__ x) {
    int warp = (blockIdx.x * blockDim.x + threadIdx.x) >> 5;
    int lane = threadIdx.x & 31;
    int r0 = warp * 4;
    if (r0 >= NN) return;

    float4 v[4];
    bool has[4];
#pragma unroll
    for (int k = 0; k < 4; k++) {
        int r = r0 + k;
        has[k] = (r < NN);
        v[k] = has[k]
            ? __ldcs(reinterpret_cast<const float4*>(x + (size_t)r * DD) + lane)
            : make_float4(0.f, 0.f, 0.f, 0.f);
    }

    float s[4];
#pragma unroll
    for (int k = 0; k < 4; k++)
        s[k] = v[k].x * v[k].x + v[k].y * v[k].y + v[k].z * v[k].z + v[k].w * v[k].w;

#pragma unroll
    for (int o = 16; o; o >>= 1) {
#pragma unroll
        for (int k = 0; k < 4; k++)
            s[k] += __shfl_xor_sync(0xFFFFFFFFu, s[k], o);
    }

#pragma unroll
    for (int k = 0; k < 4; k++) {
        if (!has[k]) continue;
        float inv = rsqrtf(s[k]);
        __half2 h[2];
        h[0] = __floats2half2_rn(v[k].x * inv, v[k].y * inv);
        h[1] = __floats2half2_rn(v[k].z * inv, v[k].w * inv);
        reinterpret_cast<uint2*>(g_xh + (size_t)(r0 + k) * DD)[lane] =
            *reinterpret_cast<uint2*>(h);
    }
}

// ---------------------------------------------------------------------------
// Kernel 2: one block (8 warps) per anchor. Half-warp per sample (16 lanes x
// float4 = 256 B coalesced row, 2 lines per LDG). TWO interleaved sample
// chains per half-warp (slots off and off+16), each with a depth-2 prefetch
// ring -> 4 LDGs in flight and 2 independent dot/shuffle/exp chains that
// ptxas interleaves into each other's latency.
// ---------------------------------------------------------------------------
__global__ __launch_bounds__(256) void loss_kernel(
    const int* __restrict__ y,
    const int* __restrict__ anchors,
    const int* __restrict__ sampled,
    float* __restrict__ out)
{
    __shared__ int2  s_iy[SS];               // (sample index, sample label)
    __shared__ float s_num[16], s_den[16], s_cnt[16];
    __shared__ int   s_last;
    __shared__ float s_red[256];

    int a    = blockIdx.x;
    int tid  = threadIdx.x;
    int lane = tid & 31;
    int warp = tid >> 5;     // 0..7
    int hw   = lane >> 4;    // half-warp id (0/1)
    int hl   = lane & 15;    // lane within half-warp

    // Stage sample indices + labels packed as int2 (random 4B gathers batched
    // here with 256 threads of MLP, out of the hot loop).
    for (int i = tid; i < SS; i += 256) {
        int si = sampled[(size_t)a * SS + i];
        s_iy[i] = make_int2(si, y[si]);
    }

    int ai = anchors[a];
    int ay = y[ai];

    // Anchor row: 8 fp16 per half-lane, kept as half2 (no conversion)
    __half2 ah[4];
    {
        float4 ar = reinterpret_cast<const float4*>(g_xh + (size_t)ai * DD)[hl];
        const __half2* p = reinterpret_cast<const __half2*>(&ar);
#pragma unroll
        for (int j = 0; j < 4; j++) ah[j] = p[j];
    }
    __syncthreads();

    const int offA = warp * 2 + hw;          // 0..15
    const int offB = offA + 16;              // 16..31
    float num = 0.0f, den = 0.0f, cnt = 0.0f;

    // Two chains, each with a depth-2 prefetch ring
    float4 bufA[2], bufB[2];
    int    yA[2],   yB[2];
#pragma unroll
    for (int p = 0; p < 2; p++) {
        int2 ia = s_iy[p * 32 + offA];
        int2 ib = s_iy[p * 32 + offB];
        bufA[p] = reinterpret_cast<const float4*>(g_xh + (size_t)ia.x * DD)[hl];
        bufB[p] = reinterpret_cast<const float4*>(g_xh + (size_t)ib.x * DD)[hl];
        yA[p] = ia.y;
        yB[p] = ib.y;
    }

#pragma unroll
    for (int it = 0; it < 16; it++) {        // 16 iterations x 32 samples
        float4 ca = bufA[it & 1]; int yca = yA[it & 1];
        float4 cb = bufB[it & 1]; int ycb = yB[it & 1];
        if (it + 2 < 16) {
            int2 ia = s_iy[(it + 2) * 32 + offA];
            int2 ib = s_iy[(it + 2) * 32 + offB];
            bufA[it & 1] = reinterpret_cast<const float4*>(g_xh + (size_t)ia.x * DD)[hl];
            bufB[it & 1] = reinterpret_cast<const float4*>(g_xh + (size_t)ib.x * DD)[hl];
            yA[it & 1] = ia.y;
            yB[it & 1] = ib.y;
        }

        // Chain A dot
        const __half2* sa = reinterpret_cast<const __half2*>(&ca);
        __half2 accA = __hmul2(ah[0], sa[0]);
        accA = __hfma2(ah[1], sa[1], accA);
        accA = __hfma2(ah[2], sa[2], accA);
        accA = __hfma2(ah[3], sa[3], accA);
        float2 fa = __half22float2(accA);
        float dA = fa.x + fa.y;

        // Chain B dot (independent)
        const __half2* sb = reinterpret_cast<const __half2*>(&cb);
        __half2 accB = __hmul2(ah[0], sb[0]);
        accB = __hfma2(ah[1], sb[1], accB);
        accB = __hfma2(ah[2], sb[2], accB);
        accB = __hfma2(ah[3], sb[3], accB);
        float2 fb = __half22float2(accB);
        float dB = fb.x + fb.y;

        // Two independent 16-lane reduces, interleaved
#pragma unroll
        for (int o = 8; o; o >>= 1) {
            dA += __shfl_xor_sync(0xFFFFFFFFu, dA, o);
            dB += __shfl_xor_sync(0xFFFFFFFFu, dB, o);
        }
        float eA = ex2_approx(dA * 14.4269504089f);   // exp(dA * 10)
        float eB = ex2_approx(dB * 14.4269504089f);
        den += eA + eB;
        if (yca == ay) { num += eA; cnt += 1.0f; }
        if (ycb == ay) { num += eB; cnt += 1.0f; }
    }

    // Sums are uniform within the half-warp
    if (hl == 0) { s_num[offA] = num; s_den[offA] = den; s_cnt[offA] = cnt; }
    __syncthreads();

    if (tid == 0) {
        float nm = 0.0f, dn = 0.0f, c = 0.0f;
#pragma unroll
        for (int k = 0; k < 16; k++) { nm += s_num[k]; dn += s_den[k]; c += s_cnt[k]; }
        float loss = 0.0f;
        if (c > 0.0f) loss = (logf(dn) - logf(nm)) / c;  // -log(num/den)/cnt
        g_aloss[a] = loss;
        __threadfence();
        int t = atomicAdd(&g_done, 1);
        s_last = (t == AA - 1) ? 1 : 0;
    }
    __syncthreads();

    // Last block to finish: deterministic fixed-order reduction of g_aloss.
    if (s_last) {
        float s = 0.0f;
        for (int i = tid; i < AA; i += 256) s += g_aloss[i];
        s_red[tid] = s;
        __syncthreads();
        for (int o = 128; o; o >>= 1) {
            if (tid < o) s_red[tid] += s_red[tid + o];
            __syncthreads();
        }
        if (tid == 0) {
            out[0] = s_red[0];
            g_done = 0;                      // reset for next graph replay
        }
    }
}

extern "C" void kernel_launch(void* const* d_in, const int* in_sizes, int n_in,
                              void* d_out, int out_size) {
    const float* x       = (const float*)d_in[0];
    const int*   y       = (const int*)  d_in[1];
    const int*   anchors = (const int*)  d_in[2];
    const int*   sampled = (const int*)  d_in[3];
    float*       out     = (float*)d_out;

    (void)in_sizes; (void)n_in; (void)out_size;

    // 4 rows per warp -> 32 rows per 256-thread block
    norm_convert_kernel<<<(NN + 31) / 32, 256>>>(x);
    loss_kernel<<<AA, 256>>>(y, anchors, sampled, out);
}